// round 3
// baseline (speedup 1.0000x reference)
#include <cuda_runtime.h>

// Shapes (fixed by the problem)
#define BB    128     // batch
#define DX    1024
#define NKK   1024    // number of keys
#define DKIN  512
#define NH    16      // heads
#define DKH   64      // d_k per head
#define HD    1024    // NH*DKH
#define DOUT  512

// ---------------- scratch (device globals; no allocation) ----------------
__device__ float g_m1[DX], g_rs1[DX];
__device__ float g_xq[BB * HD];
__device__ float g_m2[DKH], g_rs2[DKH];
__device__ float g_xhid[BB * HD];
__device__ float g_kpart[BB * 8 * DKIN];   // partial k-sums
__device__ float g_ksum[BB * DKIN];
__device__ float g_t2[BB * HD];

// ---------------- attn output is exactly all-ones ----------------
__global__ void fill_ones(float4* __restrict__ p) {
    p[blockIdx.x * 256 + threadIdx.x] = make_float4(1.f, 1.f, 1.f, 1.f);
}

// ---------------- k reduction: ksum[b][j] = sum_n k[b][n][j] ----------------
// grid = BB*8 blocks, 128 threads; each block sums 128 n-rows of one batch.
__global__ void ksum_part(const float* __restrict__ k) {
    int b = blockIdx.x >> 3, chunk = blockIdx.x & 7;
    int t = threadIdx.x;  // 0..127
    const float4* kp = (const float4*)(k + (size_t)b * NKK * DKIN
                                         + (size_t)chunk * 128 * DKIN);
    float4 acc = make_float4(0.f, 0.f, 0.f, 0.f);
    #pragma unroll 8
    for (int n = 0; n < 128; n++) {
        float4 v = kp[n * (DKIN / 4) + t];
        acc.x += v.x; acc.y += v.y; acc.z += v.z; acc.w += v.w;
    }
    ((float4*)g_kpart)[(size_t)(b * 8 + chunk) * (DKIN / 4) + t] = acc;
}

__global__ void ksum_reduce() {
    int b = blockIdx.x, j = threadIdx.x;  // block=512
    float s = 0.f;
    #pragma unroll
    for (int c = 0; c < 8; c++) s += g_kpart[(b * 8 + c) * DKIN + j];
    g_ksum[b * DKIN + j] = s;
}

// ---------------- BN1 stats over batch (biased var, eps=1e-5) ----------------
__global__ void bn1_stats(const float* __restrict__ x) {
    __shared__ float ss[8][32], sq[8][32];
    int c = threadIdx.x, r = threadIdx.y;
    int col = blockIdx.x * 32 + c;
    float s = 0.f, q = 0.f;
    for (int i = r; i < BB; i += 8) {
        float v = x[i * DX + col];
        s += v; q += v * v;
    }
    ss[r][c] = s; sq[r][c] = q;
    __syncthreads();
    if (r == 0) {
        float S = 0.f, Q = 0.f;
        #pragma unroll
        for (int i = 0; i < 8; i++) { S += ss[i][c]; Q += sq[i][c]; }
        float m = S * (1.f / BB);
        float var = Q * (1.f / BB) - m * m;
        g_m1[col] = m;
        g_rs1[col] = rsqrtf(var + 1e-5f);
    }
}

// ---------------- generic tiled GEMM: C[M,N] = A[M,K] @ W[N,K]^T + bscale*bias --------
// Optional BN transform on A elements (per-K-column affine using g_m1/g_rs1).
// 32x32 tile, 256 threads, 4 outputs/thread.
template <int KDIM, bool BN>
__global__ void gemm_abT(const float* __restrict__ A, const float* __restrict__ W,
                         const float* __restrict__ bias, float bscale,
                         const float* __restrict__ gn, const float* __restrict__ bn,
                         float* __restrict__ C, int N) {
    __shared__ float As[32][33], Ws[32][33];
    int tx = threadIdx.x & 31, ty = threadIdx.x >> 5;  // ty 0..7
    int m0 = blockIdx.y * 32, n0 = blockIdx.x * 32;
    float a0 = 0.f, a1 = 0.f, a2 = 0.f, a3 = 0.f;
    for (int k0 = 0; k0 < KDIM; k0 += 32) {
        #pragma unroll
        for (int i = 0; i < 4; i++) {
            int idx = threadIdx.x + i * 256;
            int rr = idx >> 5, cc = idx & 31;
            float v = A[(m0 + rr) * KDIM + k0 + cc];
            if (BN) {
                int kc = k0 + cc;
                v = (v - g_m1[kc]) * g_rs1[kc] * gn[kc] + bn[kc];
            }
            As[rr][cc] = v;
            Ws[rr][cc] = W[(n0 + rr) * KDIM + k0 + cc];
        }
        __syncthreads();
        #pragma unroll
        for (int kk = 0; kk < 32; kk++) {
            float wv = Ws[tx][kk];
            a0 += As[ty][kk] * wv;
            a1 += As[ty + 8][kk] * wv;
            a2 += As[ty + 16][kk] * wv;
            a3 += As[ty + 24][kk] * wv;
        }
        __syncthreads();
    }
    float bv = bias[n0 + tx] * bscale;
    C[(m0 + ty) * N + n0 + tx]      = a0 + bv;
    C[(m0 + ty + 8) * N + n0 + tx]  = a1 + bv;
    C[(m0 + ty + 16) * N + n0 + tx] = a2 + bv;
    C[(m0 + ty + 24) * N + n0 + tx] = a3 + bv;
}

// ---------------- BN2 stats over (H*B) samples per d (d = col mod 64) ----------------
__global__ void bn2_stats() {
    __shared__ float ss[256], sq[256];
    int d = blockIdx.x, t = threadIdx.x;
    float s = 0.f, q = 0.f;
    for (int i = t; i < BB * NH; i += 256) {
        int b = i >> 4, h = i & 15;
        float v = g_xq[b * HD + h * DKH + d];
        s += v; q += v * v;
    }
    ss[t] = s; sq[t] = q;
    __syncthreads();
    for (int o = 128; o > 0; o >>= 1) {
        if (t < o) { ss[t] += ss[t + o]; sq[t] += sq[t + o]; }
        __syncthreads();
    }
    if (t == 0) {
        float m = ss[0] * (1.f / (BB * NH));
        float var = sq[0] * (1.f / (BB * NH)) - m * m;
        g_m2[d] = m;
        g_rs2[d] = rsqrtf(var + 1e-5f);
    }
}

// ---------------- x_hid[b][h*64+d'] = bn2(xq row) @ Wlin^T + blin ----------------
__global__ void xhid_kernel(const float* __restrict__ Wlin, const float* __restrict__ blin,
                            const float* __restrict__ g2, const float* __restrict__ b2) {
    __shared__ float sw[DKH][DKH + 1];
    __shared__ float sa[4][DKH];
    int t = threadIdx.x;
    #pragma unroll
    for (int i = 0; i < 16; i++) {
        int idx = t + i * 256;
        sw[idx >> 6][idx & 63] = Wlin[idx];
    }
    int j = t >> 6, dp = t & 63;
    int row = blockIdx.x * 4 + j;   // row = b*16 + h
    int b = row >> 4, h = row & 15;
    float v = g_xq[b * HD + h * DKH + dp];
    sa[j][dp] = (v - g_m2[dp]) * g_rs2[dp] * g2[dp] + b2[dp];
    __syncthreads();
    float acc = blin[dp];
    #pragma unroll
    for (int d = 0; d < DKH; d++) acc += sa[j][d] * sw[dp][d];
    g_xhid[b * HD + h * DKH + dp] = acc;
}

// =====================================================================
extern "C" void kernel_launch(void* const* d_in, const int* in_sizes, int n_in,
                              void* d_out, int out_size) {
    const float* x    = (const float*)d_in[0];
    const float* k    = (const float*)d_in[1];
    const float* bn1g = (const float*)d_in[2];
    const float* bn1b = (const float*)d_in[3];
    const float* Wx   = (const float*)d_in[4];
    const float* bx   = (const float*)d_in[5];
    const float* Wk   = (const float*)d_in[6];
    const float* bk   = (const float*)d_in[7];
    const float* bn2g = (const float*)d_in[8];
    const float* bn2b = (const float*)d_in[9];
    const float* Wlin = (const float*)d_in[10];
    const float* blin = (const float*)d_in[11];
    const float* Wo   = (const float*)d_in[12];
    const float* bo   = (const float*)d_in[13];
    float* out = (float*)d_out;

    float* attn_out = out;                       // (128,16,1024) == all ones
    float* out2 = out + (size_t)BB * NH * NKK;   // (128,512)
    float* out3 = out2 + (size_t)BB * DOUT;      // (128,512)

    // Resolve device addresses of scratch globals (host shadow != device ptr!)
    float *p_ksum = nullptr, *p_t2 = nullptr, *p_xq = nullptr, *p_xhid = nullptr;
    cudaGetSymbolAddress((void**)&p_ksum, g_ksum);
    cudaGetSymbolAddress((void**)&p_t2,   g_t2);
    cudaGetSymbolAddress((void**)&p_xq,   g_xq);
    cudaGetSymbolAddress((void**)&p_xhid, g_xhid);

    // attn output: exactly 1.0 everywhere (softmax over singleton axis)
    fill_ones<<<2048, 256>>>((float4*)attn_out);

    // k path: ksum -> t2 = ksum@Wk^T + NK*bk -> out2 = t2@Wo^T + bo
    ksum_part<<<BB * 8, 128>>>(k);
    ksum_reduce<<<BB, 512>>>();
    {
        dim3 grid(HD / 32, BB / 32);
        gemm_abT<DKIN, false><<<grid, 256>>>(p_ksum, Wk, bk, (float)NKK,
                                             nullptr, nullptr, p_t2, HD);
    }
    {
        dim3 grid(DOUT / 32, BB / 32);
        gemm_abT<HD, false><<<grid, 256>>>(p_t2, Wo, bo, 1.f,
                                           nullptr, nullptr, out2, DOUT);
    }

    // x path
    bn1_stats<<<32, dim3(32, 8)>>>(x);
    {
        dim3 grid(HD / 32, BB / 32);
        gemm_abT<DX, true><<<grid, 256>>>(x, Wx, bx, 1.f, bn1g, bn1b, p_xq, HD);
    }
    bn2_stats<<<DKH, 256>>>();
    xhid_kernel<<<(BB * NH) / 4, 256>>>(Wlin, blin, bn2g, bn2b);
    {
        dim3 grid(DOUT / 32, BB / 32);
        gemm_abT<HD, false><<<grid, 256>>>(p_xhid, Wo, bo, 1.f,
                                           nullptr, nullptr, out3, DOUT);
    }

    (void)in_sizes; (void)n_in; (void)out_size;
}

// round 4
// speedup vs baseline: 1.9253x; 1.9253x over previous
#include <cuda_runtime.h>

#define BB    128
#define DX    1024
#define NKK   1024
#define DKIN  512
#define NH    16
#define DKH   64
#define HD    1024
#define DOUT  512

// ---------------- scratch (device globals) ----------------
__device__ float g_kpart[BB * 8 * DKIN];
__device__ float g_ksum[BB * DKIN];
__device__ float g_s1[DX], g_t1[DX];          // bn1 affine fold
__device__ float g_xq[BB * HD];
__device__ float g_s2[DKH], g_t2a[DKH];       // bn2 affine fold
__device__ float g_wckp[4][DOUT * DKIN];      // Wck split-K partials
__device__ float g_Wck[DOUT * DKIN];          // Wo @ Wk
__device__ float g_Wc[DOUT * HD];             // Wo . blockdiag(Wlin)
__device__ float g_bias2[DOUT], g_bias3[DOUT];

// =====================================================================
// 128x32 tile GEMM: C[128,N] += A[128,K-chunk] @ W[N,K-chunk]^T
// 256 threads, 4x4 outputs/thread, BK=16, atomicAdd epilogue.
// MODE: 0 = none, 1 = per-col affine sc/sh (full K idx), 2 = idx & 63
template <int MODE>
__device__ __forceinline__ void gemm128_tile(
    const float* __restrict__ A, int lda,
    const float* __restrict__ W, int ldw,
    float* __restrict__ C, int ldc,
    int n0, int kStart, int kLen,
    const float* __restrict__ sc, const float* __restrict__ sh)
{
    __shared__ float As[16][132];
    __shared__ float Ws[16][36];
    int t = threadIdx.x;
    int ty = t >> 3, tx = t & 7;            // ty 0..31 (rows*4), tx 0..7 (cols*4)
    float acc[4][4] = {};
    for (int k0 = kStart; k0 < kStart + kLen; k0 += 16) {
        #pragma unroll
        for (int u = 0; u < 2; u++) {
            int i = t + u * 256;
            int row = i & 127, kg = i >> 7;   // kg 0..3
            float4 a = *(const float4*)&A[(size_t)row * lda + k0 + kg * 4];
            if (MODE) {
                #pragma unroll
                for (int j = 0; j < 4; j++) {
                    int col = k0 + kg * 4 + j;
                    int ci = (MODE == 2) ? (col & 63) : col;
                    ((float*)&a)[j] = ((float*)&a)[j] * sc[ci] + sh[ci];
                }
            }
            As[kg * 4 + 0][row] = a.x; As[kg * 4 + 1][row] = a.y;
            As[kg * 4 + 2][row] = a.z; As[kg * 4 + 3][row] = a.w;
        }
        if (t < 128) {
            int n = t & 31, kg = t >> 5;      // kg 0..3
            float4 w = *(const float4*)&W[(size_t)(n0 + n) * ldw + k0 + kg * 4];
            Ws[kg * 4 + 0][n] = w.x; Ws[kg * 4 + 1][n] = w.y;
            Ws[kg * 4 + 2][n] = w.z; Ws[kg * 4 + 3][n] = w.w;
        }
        __syncthreads();
        #pragma unroll
        for (int kk = 0; kk < 16; kk++) {
            float4 a = *(const float4*)&As[kk][ty * 4];
            float4 b = *(const float4*)&Ws[kk][tx * 4];
            acc[0][0] += a.x * b.x; acc[0][1] += a.x * b.y; acc[0][2] += a.x * b.z; acc[0][3] += a.x * b.w;
            acc[1][0] += a.y * b.x; acc[1][1] += a.y * b.y; acc[1][2] += a.y * b.z; acc[1][3] += a.y * b.w;
            acc[2][0] += a.z * b.x; acc[2][1] += a.z * b.y; acc[2][2] += a.z * b.z; acc[2][3] += a.z * b.w;
            acc[3][0] += a.w * b.x; acc[3][1] += a.w * b.y; acc[3][2] += a.w * b.z; acc[3][3] += a.w * b.w;
        }
        __syncthreads();
    }
    #pragma unroll
    for (int i = 0; i < 4; i++)
        #pragma unroll
        for (int j = 0; j < 4; j++)
            atomicAdd(&C[(size_t)(ty * 4 + i) * ldc + n0 + tx * 4 + j], acc[i][j]);
}

// =====================================================================
// classic 64x64 tile, C[m0.., n0C..] = A[M,K]@B[K,N] chunk (direct store)
__device__ __forceinline__ void gemm64_tile(
    const float* __restrict__ A, int lda,   // A[M,K], K contiguous
    const float* __restrict__ B, int ldb,   // B[K,N], N contiguous
    float* __restrict__ C, int ldc,
    int m0, int n0B, int n0C, int kStart, int kLen)
{
    __shared__ float As[16][68];
    __shared__ float Bs[16][68];
    int t = threadIdx.x;
    int ty = t >> 4, tx = t & 15;
    float acc[4][4] = {};
    for (int k0 = kStart; k0 < kStart + kLen; k0 += 16) {
        {
            int m = t & 63, kg = t >> 6;     // kg 0..3
            float4 a = *(const float4*)&A[(size_t)(m0 + m) * lda + k0 + kg * 4];
            As[kg * 4 + 0][m] = a.x; As[kg * 4 + 1][m] = a.y;
            As[kg * 4 + 2][m] = a.z; As[kg * 4 + 3][m] = a.w;
        }
        {
            int n4 = t & 15, kk = t >> 4;    // kk 0..15
            float4 b = *(const float4*)&B[(size_t)(k0 + kk) * ldb + n0B + n4 * 4];
            *(float4*)&Bs[kk][n4 * 4] = b;
        }
        __syncthreads();
        #pragma unroll
        for (int kk = 0; kk < 16; kk++) {
            float4 a = *(const float4*)&As[kk][ty * 4];
            float4 b = *(const float4*)&Bs[kk][tx * 4];
            acc[0][0] += a.x * b.x; acc[0][1] += a.x * b.y; acc[0][2] += a.x * b.z; acc[0][3] += a.x * b.w;
            acc[1][0] += a.y * b.x; acc[1][1] += a.y * b.y; acc[1][2] += a.y * b.z; acc[1][3] += a.y * b.w;
            acc[2][0] += a.z * b.x; acc[2][1] += a.z * b.y; acc[2][2] += a.z * b.z; acc[2][3] += a.z * b.w;
            acc[3][0] += a.w * b.x; acc[3][1] += a.w * b.y; acc[3][2] += a.w * b.z; acc[3][3] += a.w * b.w;
        }
        __syncthreads();
    }
    #pragma unroll
    for (int i = 0; i < 4; i++)
        #pragma unroll
        for (int j = 0; j < 4; j++)
            C[(size_t)(m0 + ty * 4 + i) * ldc + n0C + tx * 4 + j] = acc[i][j];
}

// =====================================================================
// K1: everything that depends only on raw inputs. grid = 4128 x 256
__global__ void k1_kernel(const float* __restrict__ x, const float* __restrict__ k,
                          const float* __restrict__ bn1g, const float* __restrict__ bn1b,
                          const float* __restrict__ Wo, const float* __restrict__ Wk,
                          const float* __restrict__ Wlin,
                          const float* __restrict__ bk, const float* __restrict__ blin,
                          const float* __restrict__ bo, const float* __restrict__ bx,
                          float4* __restrict__ attn_out)
{
    int blk = blockIdx.x, t = threadIdx.x;
    if (blk < 1024) {
        // ---- ksum partials: block = (b, chunk of 128 rows) ----
        int b = blk >> 3, chunk = blk & 7;
        int c4 = t & 127, h = t >> 7;        // 2 row-halves x 128 float4 cols
        const float4* kp = (const float4*)(k + (size_t)b * NKK * DKIN
                                             + (size_t)chunk * 128 * DKIN);
        float4 acc = make_float4(0.f, 0.f, 0.f, 0.f);
        int base = h * 64;
        #pragma unroll 8
        for (int n = 0; n < 64; n++) {
            float4 v = kp[(size_t)(base + n) * (DKIN / 4) + c4];
            acc.x += v.x; acc.y += v.y; acc.z += v.z; acc.w += v.w;
        }
        __shared__ float4 sbuf[128];
        if (h == 1) sbuf[c4] = acc;
        __syncthreads();
        if (h == 0) {
            float4 o = sbuf[c4];
            acc.x += o.x; acc.y += o.y; acc.z += o.z; acc.w += o.w;
            ((float4*)g_kpart)[(size_t)(b * 8 + chunk) * (DKIN / 4) + c4] = acc;
        }
    } else if (blk < 1056) {
        // ---- bn1 stats -> s1/t1 ----
        __shared__ float ss[8][32], sq[8][32];
        int c = t & 31, r = t >> 5;
        int col = (blk - 1024) * 32 + c;
        float s = 0.f, q = 0.f;
        for (int i = r; i < BB; i += 8) {
            float v = x[(size_t)i * DX + col];
            s += v; q += v * v;
        }
        ss[r][c] = s; sq[r][c] = q;
        __syncthreads();
        if (r == 0) {
            float S = 0.f, Q = 0.f;
            #pragma unroll
            for (int i = 0; i < 8; i++) { S += ss[i][c]; Q += sq[i][c]; }
            float m = S * (1.f / BB);
            float var = Q * (1.f / BB) - m * m;
            float rs = rsqrtf(var + 1e-5f);
            float sc = rs * bn1g[col];
            g_s1[col] = sc;
            g_t1[col] = bn1b[col] - m * sc;
        }
    } else if (blk < 3104) {
        // ---- attn output = all ones ----
        attn_out[(size_t)(blk - 1056) * 256 + t] = make_float4(1.f, 1.f, 1.f, 1.f);
    } else if (blk < 3360) {
        // ---- Wck partials: Wo(512,1024) @ Wk(1024,512), split-K 4 ----
        int id = blk - 3104;
        int s = id >> 6, tile = id & 63;
        int m0 = (tile >> 3) * 64, n0 = (tile & 7) * 64;
        gemm64_tile(Wo, HD, Wk, DKIN, g_wckp[s], DKIN, m0, n0, n0, s * 256, 256);
    } else if (blk < 3488) {
        // ---- Wc: per-head Wo[:,h*64:] (512x64) @ Wlin (64x64) ----
        int id = blk - 3360;
        int h = id >> 3, ms = id & 7;
        gemm64_tile(Wo + h * 64, HD, Wlin, DKH, g_Wc, HD, ms * 64, 0, h * 64, 0, 64);
    } else if (blk < 3616) {
        // ---- bias2 = NK*(Wo@bk)+bo ; bias3 = Wo@blin_e+bo (warp/output) ----
        int wid = (blk - 3488) * 8 + (t >> 5), lane = t & 31;
        int o = wid & 511;
        const float* wrow = Wo + (size_t)o * HD;
        float s = 0.f;
        if (wid < 512) {
            for (int j = lane; j < HD; j += 32) s += wrow[j] * bk[j];
        } else {
            for (int j = lane; j < HD; j += 32) s += wrow[j] * blin[j & 63];
        }
        #pragma unroll
        for (int off = 16; off > 0; off >>= 1) s += __shfl_xor_sync(0xffffffffu, s, off);
        if (lane == 0) {
            if (wid < 512) g_bias2[o] = (float)NKK * s + bo[o];
            else           g_bias3[o] = s + bo[o];
        }
    } else {
        // ---- init g_xq rows with bx ----
        int idx = (blk - 3616) * 256 + t;
        g_xq[idx] = bx[idx & (HD - 1)];
    }
}

// =====================================================================
// K2: reduces + xq GEMM + out bias init. grid = 1152 x 256
__global__ void k2_kernel(const float* __restrict__ x, const float* __restrict__ Wx,
                          float* __restrict__ out2, float* __restrict__ out3)
{
    int blk = blockIdx.x, t = threadIdx.x;
    if (blk < 128) {
        int b = blk;
        #pragma unroll
        for (int jj = 0; jj < 2; jj++) {
            int j = t + jj * 256;
            float s = 0.f;
            #pragma unroll
            for (int c = 0; c < 8; c++) s += g_kpart[(size_t)(b * 8 + c) * DKIN + j];
            g_ksum[(size_t)b * DKIN + j] = s;
        }
    } else if (blk < 384) {
        // Wck reduce (float4, 4 partials)
        int i = (blk - 128) * 256 + t;
        float4 a = ((const float4*)g_wckp[0])[i];
        float4 b = ((const float4*)g_wckp[1])[i];
        float4 c = ((const float4*)g_wckp[2])[i];
        float4 d = ((const float4*)g_wckp[3])[i];
        a.x += b.x + c.x + d.x; a.y += b.y + c.y + d.y;
        a.z += b.z + c.z + d.z; a.w += b.w + c.w + d.w;
        ((float4*)g_Wck)[i] = a;
    } else if (blk < 896) {
        // out2/out3 bias init
        int idx = (blk - 384) * 256 + t;
        if (idx < BB * DOUT) out2[idx] = g_bias2[idx & (DOUT - 1)];
        else                 out3[idx - BB * DOUT] = g_bias3[idx & (DOUT - 1)];
    } else {
        // xq GEMM: (bn1 affine on x) @ Wx^T, split-K 8 (chunk 128), 32 n-stripes
        int id = blk - 896;
        int n0 = (id & 31) * 32, ks = (id >> 5) * 128;
        gemm128_tile<1>(x, DX, Wx, DX, g_xq, HD, n0, ks, 128, g_s1, g_t1);
    }
}

// =====================================================================
// K3: bn2 stats + out2 GEMM. grid = 192 x 256
__global__ void k3_kernel(const float* __restrict__ bn2g, const float* __restrict__ bn2b,
                          float* __restrict__ out2)
{
    int blk = blockIdx.x, t = threadIdx.x;
    if (blk < 64) {
        __shared__ float ss[256], sq[256];
        int d = blk;
        float s = 0.f, q = 0.f;
        for (int i = t; i < BB * NH; i += 256) {
            int b = i >> 4, h = i & 15;
            float v = g_xq[(size_t)b * HD + h * DKH + d];
            s += v; q += v * v;
        }
        ss[t] = s; sq[t] = q;
        __syncthreads();
        for (int o = 128; o > 0; o >>= 1) {
            if (t < o) { ss[t] += ss[t + o]; sq[t] += sq[t + o]; }
            __syncthreads();
        }
        if (t == 0) {
            float m = ss[0] * (1.f / (BB * NH));
            float var = sq[0] * (1.f / (BB * NH)) - m * m;
            float rs = rsqrtf(var + 1e-5f);
            float sc = rs * bn2g[d];
            g_s2[d] = sc;
            g_t2a[d] = bn2b[d] - m * sc;
        }
    } else {
        // out2 += ksum @ Wck^T ; split-K 8 (chunk 64), 16 n-stripes
        int id = blk - 64;
        int n0 = (id & 15) * 32, ks = (id >> 4) * 64;
        gemm128_tile<0>(g_ksum, DKIN, g_Wck, DKIN, out2, DOUT, n0, ks, 64, nullptr, nullptr);
    }
}

// =====================================================================
// K4: out3 GEMM. grid = 128 x 256
__global__ void k4_kernel(float* __restrict__ out3)
{
    int id = blockIdx.x;
    int n0 = (id & 15) * 32, ks = (id >> 4) * 128;
    gemm128_tile<2>(g_xq, HD, g_Wc, HD, out3, DOUT, n0, ks, 128, g_s2, g_t2a);
}

// =====================================================================
extern "C" void kernel_launch(void* const* d_in, const int* in_sizes, int n_in,
                              void* d_out, int out_size) {
    const float* x    = (const float*)d_in[0];
    const float* k    = (const float*)d_in[1];
    const float* bn1g = (const float*)d_in[2];
    const float* bn1b = (const float*)d_in[3];
    const float* Wx   = (const float*)d_in[4];
    const float* bx   = (const float*)d_in[5];
    const float* Wk   = (const float*)d_in[6];
    const float* bk   = (const float*)d_in[7];
    const float* bn2g = (const float*)d_in[8];
    const float* bn2b = (const float*)d_in[9];
    const float* Wlin = (const float*)d_in[10];
    const float* blin = (const float*)d_in[11];
    const float* Wo   = (const float*)d_in[12];
    const float* bo   = (const float*)d_in[13];
    float* out = (float*)d_out;

    float* attn_out = out;                       // (128,16,1024) == all ones
    float* out2 = out + (size_t)BB * NH * NKK;   // (128,512)
    float* out3 = out2 + (size_t)BB * DOUT;      // (128,512)

    k1_kernel<<<4128, 256>>>(x, k, bn1g, bn1b, Wo, Wk, Wlin, bk, blin, bo, bx,
                             (float4*)attn_out);
    k2_kernel<<<1152, 256>>>(x, Wx, out2, out3);
    k3_kernel<<<192, 256>>>(bn2g, bn2b, out2);
    k4_kernel<<<128, 256>>>(out3);

    (void)in_sizes; (void)n_in; (void)out_size;
}

// round 5
// speedup vs baseline: 2.1304x; 1.1065x over previous
#include <cuda_runtime.h>

#define BB    128
#define DX    1024
#define NKK   1024
#define DKIN  512
#define NH    16
#define DKH   64
#define HD    1024
#define DOUT  512

// ---------------- scratch (device globals; 16B aligned for float4) ----------------
__device__ __align__(16) float g_ksum[BB * DKIN];
__device__ __align__(16) float g_s1[DX], g_t1[DX];     // bn1 affine fold
__device__ __align__(16) float g_xq[BB * HD];
__device__ __align__(16) float g_s2[DKH], g_t2a[DKH];  // bn2 affine fold
__device__ __align__(16) float g_Wck[DOUT * DKIN];     // Wo @ Wk
__device__ __align__(16) float g_Wc[DOUT * HD];        // Wo . blockdiag(Wlin)
__device__ __align__(16) float g_bias2[DOUT], g_bias3[DOUT];

// =====================================================================
// 128x32 GEMM tile, double-buffered: C[128, n0..n0+32) += A[128,Kchunk] @ W^T
// 256 threads, 4x4 accum/thread, BK=16, atomicAdd epilogue.
// MODE: 0 none; 1 per-col affine (ssc idx = col-kStart, kLen<=256); 2 idx = col&63
template <int MODE>
__device__ __forceinline__ void gemm128(
    const float* __restrict__ A, int lda,
    const float* __restrict__ W, int ldw,
    float* __restrict__ C, int ldc,
    int n0, int kStart, int nIter,
    const float* __restrict__ gsc, const float* __restrict__ gsh)
{
    __shared__ float As[2][16][132];
    __shared__ float Ws[2][16][36];
    __shared__ float ssc[256], ssh[256];
    const int t = threadIdx.x;
    if (MODE == 1) { ssc[t] = gsc[kStart + t]; ssh[t] = gsh[kStart + t]; }
    if (MODE == 2) { if (t < 64) { ssc[t] = gsc[t]; ssh[t] = gsh[t]; } }
    if (MODE) __syncthreads();

    const int rowA = t & 127, kgA = t >> 7;   // kgA in {0,1}; second load uses kgA+2
    const int nW = t & 31, kgW = t >> 5;      // valid for t<128
    const int ty = t >> 3, tx = t & 7;

    float4 ra0, ra1, rw;
    {
        int k0 = kStart;
        ra0 = *(const float4*)&A[(size_t)rowA * lda + k0 + kgA * 4];
        ra1 = *(const float4*)&A[(size_t)rowA * lda + k0 + (kgA + 2) * 4];
        if (t < 128) rw = *(const float4*)&W[(size_t)(n0 + nW) * ldw + k0 + kgW * 4];
        // store -> buf 0
        float va[8] = {ra0.x, ra0.y, ra0.z, ra0.w, ra1.x, ra1.y, ra1.z, ra1.w};
        #pragma unroll
        for (int u = 0; u < 2; u++) {
            int kg = kgA + u * 2;
            #pragma unroll
            for (int j = 0; j < 4; j++) {
                float v = va[u * 4 + j];
                if (MODE == 1) { int ci = (k0 - kStart) + kg * 4 + j; v = v * ssc[ci] + ssh[ci]; }
                if (MODE == 2) { int ci = (k0 + kg * 4 + j) & 63;     v = v * ssc[ci] + ssh[ci]; }
                As[0][kg * 4 + j][rowA] = v;
            }
        }
        if (t < 128) {
            Ws[0][kgW * 4 + 0][nW] = rw.x; Ws[0][kgW * 4 + 1][nW] = rw.y;
            Ws[0][kgW * 4 + 2][nW] = rw.z; Ws[0][kgW * 4 + 3][nW] = rw.w;
        }
    }
    __syncthreads();

    float acc[4][4] = {};
    for (int it = 0; it < nIter; it++) {
        const int buf = it & 1;
        float4 na0, na1, nw;
        const bool more = (it + 1 < nIter);
        if (more) {
            int kn = kStart + (it + 1) * 16;
            na0 = *(const float4*)&A[(size_t)rowA * lda + kn + kgA * 4];
            na1 = *(const float4*)&A[(size_t)rowA * lda + kn + (kgA + 2) * 4];
            if (t < 128) nw = *(const float4*)&W[(size_t)(n0 + nW) * ldw + kn + kgW * 4];
        }
        #pragma unroll
        for (int kk = 0; kk < 16; kk++) {
            float4 a = *(const float4*)&As[buf][kk][ty * 4];
            float4 b = *(const float4*)&Ws[buf][kk][tx * 4];
            acc[0][0] += a.x * b.x; acc[0][1] += a.x * b.y; acc[0][2] += a.x * b.z; acc[0][3] += a.x * b.w;
            acc[1][0] += a.y * b.x; acc[1][1] += a.y * b.y; acc[1][2] += a.y * b.z; acc[1][3] += a.y * b.w;
            acc[2][0] += a.z * b.x; acc[2][1] += a.z * b.y; acc[2][2] += a.z * b.z; acc[2][3] += a.z * b.w;
            acc[3][0] += a.w * b.x; acc[3][1] += a.w * b.y; acc[3][2] += a.w * b.z; acc[3][3] += a.w * b.w;
        }
        if (more) {
            int kn = kStart + (it + 1) * 16;
            int nb = buf ^ 1;
            float va[8] = {na0.x, na0.y, na0.z, na0.w, na1.x, na1.y, na1.z, na1.w};
            #pragma unroll
            for (int u = 0; u < 2; u++) {
                int kg = kgA + u * 2;
                #pragma unroll
                for (int j = 0; j < 4; j++) {
                    float v = va[u * 4 + j];
                    if (MODE == 1) { int ci = (kn - kStart) + kg * 4 + j; v = v * ssc[ci] + ssh[ci]; }
                    if (MODE == 2) { int ci = (kn + kg * 4 + j) & 63;     v = v * ssc[ci] + ssh[ci]; }
                    As[nb][kg * 4 + j][rowA] = v;
                }
            }
            if (t < 128) {
                Ws[nb][kgW * 4 + 0][nW] = nw.x; Ws[nb][kgW * 4 + 1][nW] = nw.y;
                Ws[nb][kgW * 4 + 2][nW] = nw.z; Ws[nb][kgW * 4 + 3][nW] = nw.w;
            }
            __syncthreads();
        }
    }
    #pragma unroll
    for (int i = 0; i < 4; i++)
        #pragma unroll
        for (int j = 0; j < 4; j++)
            atomicAdd(&C[(size_t)(ty * 4 + i) * ldc + n0 + tx * 4 + j], acc[i][j]);
}

// =====================================================================
// classic 64x64 tile, C[m0.., n0C..] (+)= A[M,K]@B[K,N] chunk
template <bool ATOMIC>
__device__ __forceinline__ void gemm64(
    const float* __restrict__ A, int lda,   // A[M,K], K contiguous
    const float* __restrict__ B, int ldb,   // B[K,N], N contiguous
    float* __restrict__ C, int ldc,
    int m0, int n0B, int n0C, int kStart, int kLen)
{
    __shared__ float As[16][68];
    __shared__ float Bs[16][68];
    int t = threadIdx.x;
    int ty = t >> 4, tx = t & 15;
    float acc[4][4] = {};
    for (int k0 = kStart; k0 < kStart + kLen; k0 += 16) {
        {
            int m = t & 63, kg = t >> 6;
            float4 a = *(const float4*)&A[(size_t)(m0 + m) * lda + k0 + kg * 4];
            As[kg * 4 + 0][m] = a.x; As[kg * 4 + 1][m] = a.y;
            As[kg * 4 + 2][m] = a.z; As[kg * 4 + 3][m] = a.w;
        }
        {
            int n4 = t & 15, kk = t >> 4;
            float4 b = *(const float4*)&B[(size_t)(k0 + kk) * ldb + n0B + n4 * 4];
            *(float4*)&Bs[kk][n4 * 4] = b;
        }
        __syncthreads();
        #pragma unroll
        for (int kk = 0; kk < 16; kk++) {
            float4 a = *(const float4*)&As[kk][ty * 4];
            float4 b = *(const float4*)&Bs[kk][tx * 4];
            acc[0][0] += a.x * b.x; acc[0][1] += a.x * b.y; acc[0][2] += a.x * b.z; acc[0][3] += a.x * b.w;
            acc[1][0] += a.y * b.x; acc[1][1] += a.y * b.y; acc[1][2] += a.y * b.z; acc[1][3] += a.y * b.w;
            acc[2][0] += a.z * b.x; acc[2][1] += a.z * b.y; acc[2][2] += a.z * b.z; acc[2][3] += a.z * b.w;
            acc[3][0] += a.w * b.x; acc[3][1] += a.w * b.y; acc[3][2] += a.w * b.z; acc[3][3] += a.w * b.w;
        }
        __syncthreads();
    }
    #pragma unroll
    for (int i = 0; i < 4; i++)
        #pragma unroll
        for (int j = 0; j < 4; j++) {
            float* p = &C[(size_t)(m0 + ty * 4 + i) * ldc + n0C + tx * 4 + j];
            if (ATOMIC) atomicAdd(p, acc[i][j]); else *p = acc[i][j];
        }
}

// =====================================================================
// K0: bn1 stats + bias vectors + inits.  grid = 608 x 256
__global__ void k0_kernel(const float* __restrict__ x,
                          const float* __restrict__ bn1g, const float* __restrict__ bn1b,
                          const float* __restrict__ Wo,
                          const float* __restrict__ bk, const float* __restrict__ blin,
                          const float* __restrict__ bo, const float* __restrict__ bx)
{
    int blk = blockIdx.x, t = threadIdx.x;
    if (blk < 32) {
        // bn1 stats -> fold into affine s1/t1
        __shared__ float ss[8][32], sq[8][32];
        int c = t & 31, r = t >> 5;
        int col = blk * 32 + c;
        float s = 0.f, q = 0.f;
        for (int i = r; i < BB; i += 8) {
            float v = x[(size_t)i * DX + col];
            s += v; q += v * v;
        }
        ss[r][c] = s; sq[r][c] = q;
        __syncthreads();
        if (r == 0) {
            float S = 0.f, Q = 0.f;
            #pragma unroll
            for (int i = 0; i < 8; i++) { S += ss[i][c]; Q += sq[i][c]; }
            float m = S * (1.f / BB);
            float var = Q * (1.f / BB) - m * m;
            float sc = rsqrtf(var + 1e-5f) * bn1g[col];
            g_s1[col] = sc;
            g_t1[col] = bn1b[col] - m * sc;
        }
    } else if (blk < 160) {
        // bias2 = NK*(Wo@bk)+bo ; bias3 = Wo@blin_ext+bo   (one warp per output)
        int wid = (blk - 32) * 8 + (t >> 5), lane = t & 31;
        int o = wid & 511;
        const float* wrow = Wo + (size_t)o * HD;
        float s = 0.f;
        if (wid < 512) {
            for (int j = lane; j < HD; j += 32) s += wrow[j] * bk[j];
        } else {
            for (int j = lane; j < HD; j += 32) s += wrow[j] * blin[j & 63];
        }
        #pragma unroll
        for (int off = 16; off > 0; off >>= 1) s += __shfl_xor_sync(0xffffffffu, s, off);
        if (lane == 0) {
            if (wid < 512) g_bias2[o] = (float)NKK * s + bo[o];
            else           g_bias3[o] = s + bo[o];
        }
    } else if (blk < 288) {
        // g_xq init = bx broadcast per row
        ((float4*)g_xq)[(size_t)(blk - 160) * 256 + t] = ((const float4*)bx)[t];
    } else if (blk < 352) {
        ((float4*)g_ksum)[(size_t)(blk - 288) * 256 + t] = make_float4(0.f, 0.f, 0.f, 0.f);
    } else {
        ((float4*)g_Wck)[(size_t)(blk - 352) * 256 + t] = make_float4(0.f, 0.f, 0.f, 0.f);
    }
}

// =====================================================================
// K1: HBM-bound ksum + all input-only GEMMs + fills.  grid = 2688 x 256
__global__ void k1_kernel(const float* __restrict__ x, const float* __restrict__ k,
                          const float* __restrict__ Wx, const float* __restrict__ Wk,
                          const float* __restrict__ Wlin, const float* __restrict__ Wo,
                          float4* __restrict__ attn_out,
                          float* __restrict__ out2, float* __restrict__ out3)
{
    int blk = blockIdx.x, t = threadIdx.x;
    int ksumIdx = (blk < 512) ? blk : ((blk >= 1024 && blk < 1536) ? blk - 512 : -1);
    if (ksumIdx >= 0) {
        // ---- ksum partial (128 n-rows) -> REDG into g_ksum ----
        int b = ksumIdx >> 3, chunk = ksumIdx & 7;
        int c4 = t & 127, h = t >> 7;
        const float4* kp = (const float4*)(k + (size_t)b * NKK * DKIN
                                             + (size_t)chunk * 128 * DKIN);
        float4 acc = make_float4(0.f, 0.f, 0.f, 0.f);
        int base = h * 64;
        #pragma unroll 8
        for (int n = 0; n < 64; n++) {
            float4 v = kp[(size_t)(base + n) * (DKIN / 4) + c4];
            acc.x += v.x; acc.y += v.y; acc.z += v.z; acc.w += v.w;
        }
        __shared__ float4 sbuf[128];
        if (h) sbuf[c4] = acc;
        __syncthreads();
        if (!h) {
            float4 o = sbuf[c4];
            float* dst = &g_ksum[(size_t)b * DKIN + c4 * 4];
            atomicAdd(dst + 0, acc.x + o.x); atomicAdd(dst + 1, acc.y + o.y);
            atomicAdd(dst + 2, acc.z + o.z); atomicAdd(dst + 3, acc.w + o.w);
        }
    } else if (blk < 768) {
        // ---- Wck = Wo @ Wk, split-K 4, atomic ----
        int id = blk - 512;
        int s = id >> 6, tile = id & 63;
        gemm64<true>(Wo, HD, Wk, DKIN, g_Wck, DKIN,
                     (tile >> 3) * 64, (tile & 7) * 64, (tile & 7) * 64, s * 256, 256);
    } else if (blk < 896) {
        // ---- Wc: per-head Wo[:,h*64:] (512x64) @ Wlin (64x64) ----
        int id = blk - 768;
        int h = id >> 3, ms = id & 7;
        gemm64<false>(Wo + h * 64, HD, Wlin, DKH, g_Wc, HD, ms * 64, 0, h * 64, 0, 64);
    } else if (blk < 1024) {
        // ---- xq += bn1(x) @ Wx^T, split-K 4, atomic into bx-initialized g_xq ----
        int id = blk - 896;
        int n0 = (id & 31) * 32, s = id >> 5;
        gemm128<1>(x, DX, Wx, DX, g_xq, HD, n0, s * 256, 16, g_s1, g_t1);
    } else if (blk < 2560) {
        // ---- attn output = all ones (blk 1536..2559) ----
        size_t base = (size_t)(blk - 1536) * 512 + t * 2;
        float4 one = make_float4(1.f, 1.f, 1.f, 1.f);
        attn_out[base] = one; attn_out[base + 1] = one;
    } else {
        // ---- out2/out3 bias init ----
        int idx = (blk - 2560) * 1024 + t * 4;
        if (idx < BB * DOUT) {
            *(float4*)&out2[idx] = *(const float4*)&g_bias2[idx & (DOUT - 1)];
        } else {
            int i2 = idx - BB * DOUT;
            *(float4*)&out3[i2] = *(const float4*)&g_bias3[i2 & (DOUT - 1)];
        }
    }
}

// =====================================================================
// K2: bn2 stats + out2 GEMM.  grid = 128 x 256
__global__ void k2_kernel(const float* __restrict__ bn2g, const float* __restrict__ bn2b,
                          float* __restrict__ out2)
{
    int blk = blockIdx.x, t = threadIdx.x;
    if (blk < 64) {
        __shared__ float ss[256], sq[256];
        int d = blk;
        float s = 0.f, q = 0.f;
        for (int i = t; i < BB * NH; i += 256) {
            int b = i >> 4, h = i & 15;
            float v = g_xq[(size_t)b * HD + h * DKH + d];
            s += v; q += v * v;
        }
        ss[t] = s; sq[t] = q;
        __syncthreads();
        for (int o = 128; o > 0; o >>= 1) {
            if (t < o) { ss[t] += ss[t + o]; sq[t] += sq[t + o]; }
            __syncthreads();
        }
        if (t == 0) {
            float m = ss[0] * (1.f / (BB * NH));
            float var = sq[0] * (1.f / (BB * NH)) - m * m;
            float sc = rsqrtf(var + 1e-5f) * bn2g[d];
            g_s2[d] = sc;
            g_t2a[d] = bn2b[d] - m * sc;
        }
    } else {
        // out2 += ksum @ Wck^T : 16 n-stripes x 4 K-splits (chunk 128)
        int id = blk - 64;
        int n0 = (id & 15) * 32, s = id >> 4;
        gemm128<0>(g_ksum, DKIN, g_Wck, DKIN, out2, DOUT, n0, s * 128, 8, nullptr, nullptr);
    }
}

// =====================================================================
// K3: out3 GEMM.  grid = 64 x 256
__global__ void k3_kernel(float* __restrict__ out3)
{
    int id = blockIdx.x;
    int n0 = (id & 15) * 32, s = id >> 4;
    gemm128<2>(g_xq, HD, g_Wc, HD, out3, DOUT, n0, s * 256, 16, g_s2, g_t2a);
}

// =====================================================================
extern "C" void kernel_launch(void* const* d_in, const int* in_sizes, int n_in,
                              void* d_out, int out_size) {
    const float* x    = (const float*)d_in[0];
    const float* k    = (const float*)d_in[1];
    const float* bn1g = (const float*)d_in[2];
    const float* bn1b = (const float*)d_in[3];
    const float* Wx   = (const float*)d_in[4];
    const float* bx   = (const float*)d_in[5];
    const float* Wk   = (const float*)d_in[6];
    const float* bk   = (const float*)d_in[7];
    const float* bn2g = (const float*)d_in[8];
    const float* bn2b = (const float*)d_in[9];
    const float* Wlin = (const float*)d_in[10];
    const float* blin = (const float*)d_in[11];
    const float* Wo   = (const float*)d_in[12];
    const float* bo   = (const float*)d_in[13];
    float* out = (float*)d_out;

    float* attn_out = out;                       // (128,16,1024) == all ones
    float* out2 = out + (size_t)BB * NH * NKK;   // (128,512)
    float* out3 = out2 + (size_t)BB * DOUT;      // (128,512)

    k0_kernel<<<608, 256>>>(x, bn1g, bn1b, Wo, bk, blin, bo, bx);
    k1_kernel<<<2688, 256>>>(x, k, Wx, Wk, Wlin, Wo, (float4*)attn_out, out2, out3);
    k2_kernel<<<128, 256>>>(bn2g, bn2b, out2);
    k3_kernel<<<64, 256>>>(out3);

    (void)in_sizes; (void)n_in; (void)out_size;
}

// round 7
// speedup vs baseline: 2.6250x; 1.2321x over previous
#include <cuda_runtime.h>

#define BB    128
#define DX    1024
#define NKK   1024
#define DKIN  512
#define NH    16
#define DKH   64
#define HD    1024
#define DOUT  512

// ---------------- scratch (device globals; 16B aligned) ----------------
__device__ __align__(16) float g_ksum[BB * DKIN];
__device__ __align__(16) float g_s1[DX], g_t1[DX];     // bn1 affine fold
__device__ __align__(16) float g_xq[BB * HD];
__device__ __align__(16) float g_s2[DKH], g_t2a[DKH];  // bn2 affine fold
__device__ __align__(16) float g_t2buf[BB * HD];       // ksum @ Wk^T
__device__ __align__(16) float g_Wc[DOUT * HD];        // Wo . blockdiag(Wlin^T)
__device__ __align__(16) float g_bias2[DOUT], g_bias3[DOUT];

// =====================================================================
// 128x32 GEMM tile, double-buffered: C[128, n0..n0+32) += A[128,Kchunk] @ W^T
// 256 threads, 4x4 accum/thread, BK=16, atomicAdd epilogue.
// MODE: 0 none; 1 per-col affine (idx = col-kStart, kLen<=128); 2 idx = col&63
template <int MODE>
__device__ __forceinline__ void gemm128(
    const float* __restrict__ A, int lda,
    const float* __restrict__ W, int ldw,
    float* __restrict__ C, int ldc,
    int n0, int kStart, int nIter,
    const float* __restrict__ gsc, const float* __restrict__ gsh)
{
    __shared__ float As[2][16][132];
    __shared__ float Ws[2][16][36];
    __shared__ float ssc[128], ssh[128];
    const int t = threadIdx.x;
    if (MODE == 1) { if (t < 128) { ssc[t] = gsc[kStart + t]; ssh[t] = gsh[kStart + t]; } }
    if (MODE == 2) { if (t < 64)  { ssc[t] = gsc[t];          ssh[t] = gsh[t]; } }
    if (MODE) __syncthreads();

    const int rowA = t & 127, kgA = t >> 7;   // kgA in {0,1}; second load uses kgA+2
    const int nW = t & 31, kgW = t >> 5;      // valid for t<128
    const int ty = t >> 3, tx = t & 7;

    float4 ra0, ra1, rw;
    {
        int k0 = kStart;
        ra0 = *(const float4*)&A[(size_t)rowA * lda + k0 + kgA * 4];
        ra1 = *(const float4*)&A[(size_t)rowA * lda + k0 + (kgA + 2) * 4];
        if (t < 128) rw = *(const float4*)&W[(size_t)(n0 + nW) * ldw + k0 + kgW * 4];
        float va[8] = {ra0.x, ra0.y, ra0.z, ra0.w, ra1.x, ra1.y, ra1.z, ra1.w};
        #pragma unroll
        for (int u = 0; u < 2; u++) {
            int kg = kgA + u * 2;
            #pragma unroll
            for (int j = 0; j < 4; j++) {
                float v = va[u * 4 + j];
                if (MODE == 1) { int ci = kg * 4 + j;              v = v * ssc[ci] + ssh[ci]; }
                if (MODE == 2) { int ci = (k0 + kg * 4 + j) & 63;  v = v * ssc[ci] + ssh[ci]; }
                As[0][kg * 4 + j][rowA] = v;
            }
        }
        if (t < 128) {
            Ws[0][kgW * 4 + 0][nW] = rw.x; Ws[0][kgW * 4 + 1][nW] = rw.y;
            Ws[0][kgW * 4 + 2][nW] = rw.z; Ws[0][kgW * 4 + 3][nW] = rw.w;
        }
    }
    __syncthreads();

    float acc[4][4] = {};
    for (int it = 0; it < nIter; it++) {
        const int buf = it & 1;
        float4 na0, na1, nw;
        const bool more = (it + 1 < nIter);
        if (more) {
            int kn = kStart + (it + 1) * 16;
            na0 = *(const float4*)&A[(size_t)rowA * lda + kn + kgA * 4];
            na1 = *(const float4*)&A[(size_t)rowA * lda + kn + (kgA + 2) * 4];
            if (t < 128) nw = *(const float4*)&W[(size_t)(n0 + nW) * ldw + kn + kgW * 4];
        }
        #pragma unroll
        for (int kk = 0; kk < 16; kk++) {
            float4 a = *(const float4*)&As[buf][kk][ty * 4];
            float4 b = *(const float4*)&Ws[buf][kk][tx * 4];
            acc[0][0] += a.x * b.x; acc[0][1] += a.x * b.y; acc[0][2] += a.x * b.z; acc[0][3] += a.x * b.w;
            acc[1][0] += a.y * b.x; acc[1][1] += a.y * b.y; acc[1][2] += a.y * b.z; acc[1][3] += a.y * b.w;
            acc[2][0] += a.z * b.x; acc[2][1] += a.z * b.y; acc[2][2] += a.z * b.z; acc[2][3] += a.z * b.w;
            acc[3][0] += a.w * b.x; acc[3][1] += a.w * b.y; acc[3][2] += a.w * b.z; acc[3][3] += a.w * b.w;
        }
        if (more) {
            int kn = kStart + (it + 1) * 16;
            int nb = buf ^ 1;
            float va[8] = {na0.x, na0.y, na0.z, na0.w, na1.x, na1.y, na1.z, na1.w};
            #pragma unroll
            for (int u = 0; u < 2; u++) {
                int kg = kgA + u * 2;
                #pragma unroll
                for (int j = 0; j < 4; j++) {
                    float v = va[u * 4 + j];
                    if (MODE == 1) { int ci = (kn - kStart) + kg * 4 + j; v = v * ssc[ci] + ssh[ci]; }
                    if (MODE == 2) { int ci = (kn + kg * 4 + j) & 63;     v = v * ssc[ci] + ssh[ci]; }
                    As[nb][kg * 4 + j][rowA] = v;
                }
            }
            if (t < 128) {
                Ws[nb][kgW * 4 + 0][nW] = nw.x; Ws[nb][kgW * 4 + 1][nW] = nw.y;
                Ws[nb][kgW * 4 + 2][nW] = nw.z; Ws[nb][kgW * 4 + 3][nW] = nw.w;
            }
            __syncthreads();
        }
    }
    #pragma unroll
    for (int i = 0; i < 4; i++)
        #pragma unroll
        for (int j = 0; j < 4; j++)
            atomicAdd(&C[(size_t)(ty * 4 + i) * ldc + n0 + tx * 4 + j], acc[i][j]);
}

// =====================================================================
// classic 64x64 tile, C[m0.., n0C..] = A[M,K]@B[K,N] chunk (direct store)
__device__ __forceinline__ void gemm64(
    const float* __restrict__ A, int lda,   // A[M,K], K contiguous
    const float* __restrict__ B, int ldb,   // B[K,N], N contiguous
    float* __restrict__ C, int ldc,
    int m0, int n0B, int n0C, int kStart, int kLen)
{
    __shared__ float As[16][68];
    __shared__ float Bs[16][68];
    int t = threadIdx.x;
    int ty = t >> 4, tx = t & 15;
    float acc[4][4] = {};
    for (int k0 = kStart; k0 < kStart + kLen; k0 += 16) {
        {
            int m = t & 63, kg = t >> 6;
            float4 a = *(const float4*)&A[(size_t)(m0 + m) * lda + k0 + kg * 4];
            As[kg * 4 + 0][m] = a.x; As[kg * 4 + 1][m] = a.y;
            As[kg * 4 + 2][m] = a.z; As[kg * 4 + 3][m] = a.w;
        }
        {
            int n4 = t & 15, kk = t >> 4;
            float4 b = *(const float4*)&B[(size_t)(k0 + kk) * ldb + n0B + n4 * 4];
            *(float4*)&Bs[kk][n4 * 4] = b;
        }
        __syncthreads();
        #pragma unroll
        for (int kk = 0; kk < 16; kk++) {
            float4 a = *(const float4*)&As[kk][ty * 4];
            float4 b = *(const float4*)&Bs[kk][tx * 4];
            acc[0][0] += a.x * b.x; acc[0][1] += a.x * b.y; acc[0][2] += a.x * b.z; acc[0][3] += a.x * b.w;
            acc[1][0] += a.y * b.x; acc[1][1] += a.y * b.y; acc[1][2] += a.y * b.z; acc[1][3] += a.y * b.w;
            acc[2][0] += a.z * b.x; acc[2][1] += a.z * b.y; acc[2][2] += a.z * b.z; acc[2][3] += a.z * b.w;
            acc[3][0] += a.w * b.x; acc[3][1] += a.w * b.y; acc[3][2] += a.w * b.z; acc[3][3] += a.w * b.w;
        }
        __syncthreads();
    }
    #pragma unroll
    for (int i = 0; i < 4; i++)
        #pragma unroll
        for (int j = 0; j < 4; j++)
            C[(size_t)(m0 + ty * 4 + i) * ldc + n0C + tx * 4 + j] = acc[i][j];
}

// =====================================================================
// K0: bn1 stats + bias vectors + zero/bias inits.  grid = 480 x 256
__global__ void k0_kernel(const float* __restrict__ x,
                          const float* __restrict__ bn1g, const float* __restrict__ bn1b,
                          const float* __restrict__ Wo,
                          const float* __restrict__ bk, const float* __restrict__ blin,
                          const float* __restrict__ bo, const float* __restrict__ bx)
{
    int blk = blockIdx.x, t = threadIdx.x;
    if (blk < 32) {
        __shared__ float ss[8][32], sq[8][32];
        int c = t & 31, r = t >> 5;
        int col = blk * 32 + c;
        float s = 0.f, q = 0.f;
        for (int i = r; i < BB; i += 8) {
            float v = x[(size_t)i * DX + col];
            s += v; q += v * v;
        }
        ss[r][c] = s; sq[r][c] = q;
        __syncthreads();
        if (r == 0) {
            float S = 0.f, Q = 0.f;
            #pragma unroll
            for (int i = 0; i < 8; i++) { S += ss[i][c]; Q += sq[i][c]; }
            float m = S * (1.f / BB);
            float var = Q * (1.f / BB) - m * m;
            float sc = rsqrtf(var + 1e-5f) * bn1g[col];
            g_s1[col] = sc;
            g_t1[col] = bn1b[col] - m * sc;
        }
    } else if (blk < 160) {
        // bias2 = NK*(Wo@bk)+bo ; bias3 = Wo@blin_ext+bo  (one warp per output)
        int wid = (blk - 32) * 8 + (t >> 5), lane = t & 31;
        int o = wid & 511;
        const float* wrow = Wo + (size_t)o * HD;
        float s = 0.f;
        if (wid < 512) {
            for (int j = lane; j < HD; j += 32) s += wrow[j] * bk[j];
        } else {
            for (int j = lane; j < HD; j += 32) s += wrow[j] * blin[j & 63];
        }
        #pragma unroll
        for (int off = 16; off > 0; off >>= 1) s += __shfl_xor_sync(0xffffffffu, s, off);
        if (lane == 0) {
            if (wid < 512) g_bias2[o] = (float)NKK * s + bo[o];
            else           g_bias3[o] = s + bo[o];
        }
    } else if (blk < 288) {
        ((float4*)g_xq)[(size_t)(blk - 160) * 256 + t] = ((const float4*)bx)[t];
    } else if (blk < 352) {
        ((float4*)g_ksum)[(size_t)(blk - 288) * 256 + t] = make_float4(0.f, 0.f, 0.f, 0.f);
    } else {
        ((float4*)g_t2buf)[(size_t)(blk - 352) * 256 + t] = make_float4(0.f, 0.f, 0.f, 0.f);
    }
}

// =====================================================================
// K1: HBM-bound ksum + xq GEMM + Wc + fills.  grid = 2560 x 256
__global__ void __launch_bounds__(256, 4)
k1_kernel(const float* __restrict__ x, const float* __restrict__ k,
          const float* __restrict__ Wx, const float* __restrict__ Wlin,
          const float* __restrict__ Wo,
          float4* __restrict__ attn_out,
          float* __restrict__ out2, float* __restrict__ out3)
{
    int blk = blockIdx.x, t = threadIdx.x;
    int ksumIdx = (blk < 512) ? blk : ((blk >= 768 && blk < 1280) ? blk - 256 : -1);
    if (ksumIdx >= 0) {
        // ---- ksum partial (128 n-rows) -> REDG into g_ksum ----
        int b = ksumIdx >> 3, chunk = ksumIdx & 7;
        int c4 = t & 127, h = t >> 7;
        const float4* kp = (const float4*)(k + (size_t)b * NKK * DKIN
                                             + (size_t)chunk * 128 * DKIN);
        float4 acc = make_float4(0.f, 0.f, 0.f, 0.f);
        int base = h * 64;
        #pragma unroll 8
        for (int n = 0; n < 64; n++) {
            float4 v = kp[(size_t)(base + n) * (DKIN / 4) + c4];
            acc.x += v.x; acc.y += v.y; acc.z += v.z; acc.w += v.w;
        }
        __shared__ float4 sbuf[128];
        if (h) sbuf[c4] = acc;
        __syncthreads();
        if (!h) {
            float4 o = sbuf[c4];
            float* dst = &g_ksum[(size_t)b * DKIN + c4 * 4];
            atomicAdd(dst + 0, acc.x + o.x); atomicAdd(dst + 1, acc.y + o.y);
            atomicAdd(dst + 2, acc.z + o.z); atomicAdd(dst + 3, acc.w + o.w);
        }
    } else if (blk < 768) {
        // ---- xq += bn1(x) @ Wx^T : 32 stripes x splitK 8 (chunk 128) = 256 blocks ----
        int id = blk - 512;
        int n0 = (id & 31) * 32, s = id >> 5;
        gemm128<1>(x, DX, Wx, DX, g_xq, HD, n0, s * 128, 8, g_s1, g_t1);
    } else if (blk < 1408) {
        // ---- Wc: per-head Wo[:,h*64:] (512x64) @ Wlin (64x64) : 128 blocks ----
        int id = blk - 1280;
        int h = id >> 3, ms = id & 7;
        gemm64(Wo + h * 64, HD, Wlin, DKH, g_Wc, HD, ms * 64, 0, h * 64, 0, 64);
    } else if (blk < 2432) {
        // ---- attn output = all ones ----
        size_t base = (size_t)(blk - 1408) * 512 + t * 2;
        float4 one = make_float4(1.f, 1.f, 1.f, 1.f);
        attn_out[base] = one; attn_out[base + 1] = one;
    } else {
        // ---- out2/out3 bias init ----
        int idx = (blk - 2432) * 1024 + t * 4;
        if (idx < BB * DOUT) {
            *(float4*)&out2[idx] = *(const float4*)&g_bias2[idx & (DOUT - 1)];
        } else {
            int i2 = idx - BB * DOUT;
            *(float4*)&out3[i2] = *(const float4*)&g_bias3[i2 & (DOUT - 1)];
        }
    }
}

// =====================================================================
// K2: bn2 stats + t2 = ksum @ Wk^T.  grid = 192 x 256
__global__ void __launch_bounds__(256, 4)
k2_kernel(const float* __restrict__ bn2g, const float* __restrict__ bn2b,
          const float* __restrict__ Wk)
{
    int blk = blockIdx.x, t = threadIdx.x;
    if (blk < 64) {
        __shared__ float ss[256], sq[256];
        int d = blk;
        float s = 0.f, q = 0.f;
        for (int i = t; i < BB * NH; i += 256) {
            int b = i >> 4, h = i & 15;
            float v = g_xq[(size_t)b * HD + h * DKH + d];
            s += v; q += v * v;
        }
        ss[t] = s; sq[t] = q;
        __syncthreads();
        for (int o = 128; o > 0; o >>= 1) {
            if (t < o) { ss[t] += ss[t + o]; sq[t] += sq[t + o]; }
            __syncthreads();
        }
        if (t == 0) {
            float m = ss[0] * (1.f / (BB * NH));
            float var = sq[0] * (1.f / (BB * NH)) - m * m;
            float sc = rsqrtf(var + 1e-5f) * bn2g[d];
            g_s2[d] = sc;
            g_t2a[d] = bn2b[d] - m * sc;
        }
    } else {
        // t2 += ksum @ Wk^T : 32 stripes x splitK 4 (chunk 128) = 128 blocks
        int id = blk - 64;
        int n0 = (id & 31) * 32, s = id >> 5;
        gemm128<0>(g_ksum, DKIN, Wk, DKIN, g_t2buf, HD, n0, s * 128, 8, nullptr, nullptr);
    }
}

// =====================================================================
// K3: out2 = t2 @ Wo^T ; out3 = bn2(xq) @ Wc^T.  grid = 256 x 256
__global__ void __launch_bounds__(256, 4)
k3_kernel(const float* __restrict__ Wo, float* __restrict__ out2, float* __restrict__ out3)
{
    int blk = blockIdx.x;
    if (blk < 128) {
        int n0 = (blk & 15) * 32, s = blk >> 4;   // 16 stripes x splitK 8 (chunk 128)
        gemm128<0>(g_t2buf, HD, Wo, HD, out2, DOUT, n0, s * 128, 8, nullptr, nullptr);
    } else {
        int id = blk - 128;
        int n0 = (id & 15) * 32, s = id >> 4;
        gemm128<2>(g_xq, HD, g_Wc, HD, out3, DOUT, n0, s * 128, 8, g_s2, g_t2a);
    }
}

// =====================================================================
extern "C" void kernel_launch(void* const* d_in, const int* in_sizes, int n_in,
                              void* d_out, int out_size) {
    const float* x    = (const float*)d_in[0];
    const float* k    = (const float*)d_in[1];
    const float* bn1g = (const float*)d_in[2];
    const float* bn1b = (const float*)d_in[3];
    const float* Wx   = (const float*)d_in[4];
    const float* bx   = (const float*)d_in[5];
    const float* Wk   = (const float*)d_in[6];
    const float* bk   = (const float*)d_in[7];
    const float* bn2g = (const float*)d_in[8];
    const float* bn2b = (const float*)d_in[9];
    const float* Wlin = (const float*)d_in[10];
    const float* blin = (const float*)d_in[11];
    const float* Wo   = (const float*)d_in[12];
    const float* bo   = (const float*)d_in[13];
    float* out = (float*)d_out;

    float* attn_out = out;                       // (128,16,1024) == all ones
    float* out2 = out + (size_t)BB * NH * NKK;   // (128,512)
    float* out3 = out2 + (size_t)BB * DOUT;      // (128,512)

    k0_kernel<<<480, 256>>>(x, bn1g, bn1b, Wo, bk, blin, bo, bx);
    k1_kernel<<<2560, 256>>>(x, k, Wx, Wlin, Wo, (float4*)attn_out, out2, out3);
    k2_kernel<<<192, 256>>>(bn2g, bn2b, Wk);
    k3_kernel<<<256, 256>>>(Wo, out2, out3);

    (void)in_sizes; (void)n_in; (void)out_size;
}

// round 8
// speedup vs baseline: 2.6781x; 1.0202x over previous
#include <cuda_runtime.h>

#define BB    128
#define DX    1024
#define NKK   1024
#define DKIN  512
#define NH    16
#define DKH   64
#define HD    1024
#define DOUT  512

// ---------------- scratch (device globals; 16B aligned) ----------------
__device__ __align__(16) float g_ksum[BB * DKIN];
__device__ __align__(16) float g_s1[DX], g_t1[DX];     // bn1 affine fold
__device__ __align__(16) float g_xq[BB * HD];
__device__ __align__(16) float g_s2[DKH], g_t2a[DKH];  // bn2 affine fold
__device__ __align__(16) float g_t2buf[BB * HD];       // ksum @ Wk^T
__device__ __align__(16) float g_Wc[DOUT * HD];        // Wo . blockdiag(Wlin^T)
__device__ __align__(16) float g_bias2[DOUT], g_bias3[DOUT];

// =====================================================================
// 128x32 GEMM tile, double-buffered: C[128, n0..n0+32) += A[128,Kchunk] @ W^T
// 256 threads, 4x4 accum/thread, BK=16, atomicAdd epilogue.
// MODE: 0 none; 1 per-col affine (idx = col-kStart, kLen<=128); 2 idx = col&63
template <int MODE>
__device__ __forceinline__ void gemm128(
    const float* __restrict__ A, int lda,
    const float* __restrict__ W, int ldw,
    float* __restrict__ C, int ldc,
    int n0, int kStart, int nIter,
    const float* __restrict__ gsc, const float* __restrict__ gsh)
{
    __shared__ float As[2][16][132];
    __shared__ float Ws[2][16][36];
    __shared__ float ssc[128], ssh[128];
    const int t = threadIdx.x;
    if (MODE == 1) { if (t < 128) { ssc[t] = gsc[kStart + t]; ssh[t] = gsh[kStart + t]; } }
    if (MODE == 2) { if (t < 64)  { ssc[t] = gsc[t];          ssh[t] = gsh[t]; } }
    if (MODE) __syncthreads();

    const int rowA = t & 127, kgA = t >> 7;   // kgA in {0,1}; second load uses kgA+2
    const int nW = t & 31, kgW = t >> 5;      // valid for t<128
    const int ty = t >> 3, tx = t & 7;

    float4 ra0, ra1, rw;
    {
        int k0 = kStart;
        ra0 = *(const float4*)&A[(size_t)rowA * lda + k0 + kgA * 4];
        ra1 = *(const float4*)&A[(size_t)rowA * lda + k0 + (kgA + 2) * 4];
        if (t < 128) rw = *(const float4*)&W[(size_t)(n0 + nW) * ldw + k0 + kgW * 4];
        float va[8] = {ra0.x, ra0.y, ra0.z, ra0.w, ra1.x, ra1.y, ra1.z, ra1.w};
        #pragma unroll
        for (int u = 0; u < 2; u++) {
            int kg = kgA + u * 2;
            #pragma unroll
            for (int j = 0; j < 4; j++) {
                float v = va[u * 4 + j];
                if (MODE == 1) { int ci = kg * 4 + j;              v = v * ssc[ci] + ssh[ci]; }
                if (MODE == 2) { int ci = (k0 + kg * 4 + j) & 63;  v = v * ssc[ci] + ssh[ci]; }
                As[0][kg * 4 + j][rowA] = v;
            }
        }
        if (t < 128) {
            Ws[0][kgW * 4 + 0][nW] = rw.x; Ws[0][kgW * 4 + 1][nW] = rw.y;
            Ws[0][kgW * 4 + 2][nW] = rw.z; Ws[0][kgW * 4 + 3][nW] = rw.w;
        }
    }
    __syncthreads();

    float acc[4][4] = {};
    for (int it = 0; it < nIter; it++) {
        const int buf = it & 1;
        float4 na0, na1, nw;
        const bool more = (it + 1 < nIter);
        if (more) {
            int kn = kStart + (it + 1) * 16;
            na0 = *(const float4*)&A[(size_t)rowA * lda + kn + kgA * 4];
            na1 = *(const float4*)&A[(size_t)rowA * lda + kn + (kgA + 2) * 4];
            if (t < 128) nw = *(const float4*)&W[(size_t)(n0 + nW) * ldw + kn + kgW * 4];
        }
        #pragma unroll
        for (int kk = 0; kk < 16; kk++) {
            float4 a = *(const float4*)&As[buf][kk][ty * 4];
            float4 b = *(const float4*)&Ws[buf][kk][tx * 4];
            acc[0][0] += a.x * b.x; acc[0][1] += a.x * b.y; acc[0][2] += a.x * b.z; acc[0][3] += a.x * b.w;
            acc[1][0] += a.y * b.x; acc[1][1] += a.y * b.y; acc[1][2] += a.y * b.z; acc[1][3] += a.y * b.w;
            acc[2][0] += a.z * b.x; acc[2][1] += a.z * b.y; acc[2][2] += a.z * b.z; acc[2][3] += a.z * b.w;
            acc[3][0] += a.w * b.x; acc[3][1] += a.w * b.y; acc[3][2] += a.w * b.z; acc[3][3] += a.w * b.w;
        }
        if (more) {
            int kn = kStart + (it + 1) * 16;
            int nb = buf ^ 1;
            float va[8] = {na0.x, na0.y, na0.z, na0.w, na1.x, na1.y, na1.z, na1.w};
            #pragma unroll
            for (int u = 0; u < 2; u++) {
                int kg = kgA + u * 2;
                #pragma unroll
                for (int j = 0; j < 4; j++) {
                    float v = va[u * 4 + j];
                    if (MODE == 1) { int ci = (kn - kStart) + kg * 4 + j; v = v * ssc[ci] + ssh[ci]; }
                    if (MODE == 2) { int ci = (kn + kg * 4 + j) & 63;     v = v * ssc[ci] + ssh[ci]; }
                    As[nb][kg * 4 + j][rowA] = v;
                }
            }
            if (t < 128) {
                Ws[nb][kgW * 4 + 0][nW] = nw.x; Ws[nb][kgW * 4 + 1][nW] = nw.y;
                Ws[nb][kgW * 4 + 2][nW] = nw.z; Ws[nb][kgW * 4 + 3][nW] = nw.w;
            }
            __syncthreads();
        }
    }
    #pragma unroll
    for (int i = 0; i < 4; i++)
        #pragma unroll
        for (int j = 0; j < 4; j++)
            atomicAdd(&C[(size_t)(ty * 4 + i) * ldc + n0 + tx * 4 + j], acc[i][j]);
}

// =====================================================================
// classic 64x64 tile, C[m0.., n0C..] = A[M,K]@B[K,N] chunk (direct store)
__device__ __forceinline__ void gemm64(
    const float* __restrict__ A, int lda,   // A[M,K], K contiguous
    const float* __restrict__ B, int ldb,   // B[K,N], N contiguous
    float* __restrict__ C, int ldc,
    int m0, int n0B, int n0C, int kStart, int kLen)
{
    __shared__ float As[16][68];
    __shared__ float Bs[16][68];
    int t = threadIdx.x;
    int ty = t >> 4, tx = t & 15;
    float acc[4][4] = {};
    for (int k0 = kStart; k0 < kStart + kLen; k0 += 16) {
        {
            int m = t & 63, kg = t >> 6;
            float4 a = *(const float4*)&A[(size_t)(m0 + m) * lda + k0 + kg * 4];
            As[kg * 4 + 0][m] = a.x; As[kg * 4 + 1][m] = a.y;
            As[kg * 4 + 2][m] = a.z; As[kg * 4 + 3][m] = a.w;
        }
        {
            int n4 = t & 15, kk = t >> 4;
            float4 b = *(const float4*)&B[(size_t)(k0 + kk) * ldb + n0B + n4 * 4];
            *(float4*)&Bs[kk][n4 * 4] = b;
        }
        __syncthreads();
        #pragma unroll
        for (int kk = 0; kk < 16; kk++) {
            float4 a = *(const float4*)&As[kk][ty * 4];
            float4 b = *(const float4*)&Bs[kk][tx * 4];
            acc[0][0] += a.x * b.x; acc[0][1] += a.x * b.y; acc[0][2] += a.x * b.z; acc[0][3] += a.x * b.w;
            acc[1][0] += a.y * b.x; acc[1][1] += a.y * b.y; acc[1][2] += a.y * b.z; acc[1][3] += a.y * b.w;
            acc[2][0] += a.z * b.x; acc[2][1] += a.z * b.y; acc[2][2] += a.z * b.z; acc[2][3] += a.z * b.w;
            acc[3][0] += a.w * b.x; acc[3][1] += a.w * b.y; acc[3][2] += a.w * b.z; acc[3][3] += a.w * b.w;
        }
        __syncthreads();
    }
    #pragma unroll
    for (int i = 0; i < 4; i++)
        #pragma unroll
        for (int j = 0; j < 4; j++)
            C[(size_t)(m0 + ty * 4 + i) * ldc + n0C + tx * 4 + j] = acc[i][j];
}

// =====================================================================
// K0: bn1 stats + bias vectors + zero/bias inits.  grid = 480 x 256
__global__ void k0_kernel(const float* __restrict__ x,
                          const float* __restrict__ bn1g, const float* __restrict__ bn1b,
                          const float* __restrict__ Wo,
                          const float* __restrict__ bk, const float* __restrict__ blin,
                          const float* __restrict__ bo, const float* __restrict__ bx)
{
    int blk = blockIdx.x, t = threadIdx.x;
    if (blk < 32) {
        __shared__ float ss[8][32], sq[8][32];
        int c = t & 31, r = t >> 5;
        int col = blk * 32 + c;
        float s = 0.f, q = 0.f;
        for (int i = r; i < BB; i += 8) {
            float v = x[(size_t)i * DX + col];
            s += v; q += v * v;
        }
        ss[r][c] = s; sq[r][c] = q;
        __syncthreads();
        if (r == 0) {
            float S = 0.f, Q = 0.f;
            #pragma unroll
            for (int i = 0; i < 8; i++) { S += ss[i][c]; Q += sq[i][c]; }
            float m = S * (1.f / BB);
            float var = Q * (1.f / BB) - m * m;
            float sc = rsqrtf(var + 1e-5f) * bn1g[col];
            g_s1[col] = sc;
            g_t1[col] = bn1b[col] - m * sc;
        }
    } else if (blk < 160) {
        // bias2 = NK*(Wo@bk)+bo ; bias3 = Wo@blin_ext+bo  (one warp per output)
        int wid = (blk - 32) * 8 + (t >> 5), lane = t & 31;
        int o = wid & 511;
        const float* wrow = Wo + (size_t)o * HD;
        float s = 0.f;
        if (wid < 512) {
            for (int j = lane; j < HD; j += 32) s += wrow[j] * bk[j];
        } else {
            for (int j = lane; j < HD; j += 32) s += wrow[j] * blin[j & 63];
        }
        #pragma unroll
        for (int off = 16; off > 0; off >>= 1) s += __shfl_xor_sync(0xffffffffu, s, off);
        if (lane == 0) {
            if (wid < 512) g_bias2[o] = (float)NKK * s + bo[o];
            else           g_bias3[o] = s + bo[o];
        }
    } else if (blk < 288) {
        ((float4*)g_xq)[(size_t)(blk - 160) * 256 + t] = ((const float4*)bx)[t];
    } else if (blk < 352) {
        ((float4*)g_ksum)[(size_t)(blk - 288) * 256 + t] = make_float4(0.f, 0.f, 0.f, 0.f);
    } else {
        ((float4*)g_t2buf)[(size_t)(blk - 352) * 256 + t] = make_float4(0.f, 0.f, 0.f, 0.f);
    }
}

// =====================================================================
// K1: HBM-bound ksum + xq GEMM + Wc + fills.  grid = 2560 x 256
__global__ void __launch_bounds__(256, 4)
k1_kernel(const float* __restrict__ x, const float* __restrict__ k,
          const float* __restrict__ Wx, const float* __restrict__ Wlin,
          const float* __restrict__ Wo,
          float4* __restrict__ attn_out,
          float* __restrict__ out2, float* __restrict__ out3)
{
    int blk = blockIdx.x, t = threadIdx.x;
    int ksumIdx = (blk < 512) ? blk : ((blk >= 768 && blk < 1280) ? blk - 256 : -1);
    if (ksumIdx >= 0) {
        // ---- ksum partial (128 n-rows) -> REDG into g_ksum ----
        int b = ksumIdx >> 3, chunk = ksumIdx & 7;
        int c4 = t & 127, h = t >> 7;
        const float4* kp = (const float4*)(k + (size_t)b * NKK * DKIN
                                             + (size_t)chunk * 128 * DKIN);
        float4 acc = make_float4(0.f, 0.f, 0.f, 0.f);
        int base = h * 64;
        #pragma unroll 8
        for (int n = 0; n < 64; n++) {
            float4 v = kp[(size_t)(base + n) * (DKIN / 4) + c4];
            acc.x += v.x; acc.y += v.y; acc.z += v.z; acc.w += v.w;
        }
        __shared__ float4 sbuf[128];
        if (h) sbuf[c4] = acc;
        __syncthreads();
        if (!h) {
            float4 o = sbuf[c4];
            float* dst = &g_ksum[(size_t)b * DKIN + c4 * 4];
            atomicAdd(dst + 0, acc.x + o.x); atomicAdd(dst + 1, acc.y + o.y);
            atomicAdd(dst + 2, acc.z + o.z); atomicAdd(dst + 3, acc.w + o.w);
        }
    } else if (blk < 768) {
        // ---- xq += bn1(x) @ Wx^T : 32 stripes x splitK 8 (chunk 128) = 256 blocks ----
        int id = blk - 512;
        int n0 = (id & 31) * 32, s = id >> 5;
        gemm128<1>(x, DX, Wx, DX, g_xq, HD, n0, s * 128, 8, g_s1, g_t1);
    } else if (blk < 1408) {
        // ---- Wc: per-head Wo[:,h*64:] (512x64) @ Wlin (64x64) : 128 blocks ----
        int id = blk - 1280;
        int h = id >> 3, ms = id & 7;
        gemm64(Wo + h * 64, HD, Wlin, DKH, g_Wc, HD, ms * 64, 0, h * 64, 0, 64);
    } else if (blk < 2432) {
        // ---- attn output = all ones ----
        size_t base = (size_t)(blk - 1408) * 512 + t * 2;
        float4 one = make_float4(1.f, 1.f, 1.f, 1.f);
        attn_out[base] = one; attn_out[base + 1] = one;
    } else {
        // ---- out2/out3 bias init ----
        int idx = (blk - 2432) * 1024 + t * 4;
        if (idx < BB * DOUT) {
            *(float4*)&out2[idx] = *(const float4*)&g_bias2[idx & (DOUT - 1)];
        } else {
            int i2 = idx - BB * DOUT;
            *(float4*)&out3[i2] = *(const float4*)&g_bias3[i2 & (DOUT - 1)];
        }
    }
}

// =====================================================================
// K2: bn2 stats + t2 = ksum @ Wk^T.  grid = 320 x 256
__global__ void __launch_bounds__(256, 4)
k2_kernel(const float* __restrict__ bn2g, const float* __restrict__ bn2b,
          const float* __restrict__ Wk)
{
    int blk = blockIdx.x, t = threadIdx.x;
    if (blk < 64) {
        __shared__ float ss[256], sq[256];
        int d = blk;
        float s = 0.f, q = 0.f;
        for (int i = t; i < BB * NH; i += 256) {
            int b = i >> 4, h = i & 15;
            float v = g_xq[(size_t)b * HD + h * DKH + d];
            s += v; q += v * v;
        }
        ss[t] = s; sq[t] = q;
        __syncthreads();
        for (int o = 128; o > 0; o >>= 1) {
            if (t < o) { ss[t] += ss[t + o]; sq[t] += sq[t + o]; }
            __syncthreads();
        }
        if (t == 0) {
            float m = ss[0] * (1.f / (BB * NH));
            float var = sq[0] * (1.f / (BB * NH)) - m * m;
            float sc = rsqrtf(var + 1e-5f) * bn2g[d];
            g_s2[d] = sc;
            g_t2a[d] = bn2b[d] - m * sc;
        }
    } else {
        // t2 += ksum @ Wk^T : 32 stripes x splitK 8 (chunk 64) = 256 blocks
        int id = blk - 64;
        int n0 = (id & 31) * 32, s = id >> 5;
        gemm128<0>(g_ksum, DKIN, Wk, DKIN, g_t2buf, HD, n0, s * 64, 4, nullptr, nullptr);
    }
}

// =====================================================================
// K3: out2 = t2 @ Wo^T ; out3 = bn2(xq) @ Wc^T.  grid = 512 x 256
__global__ void __launch_bounds__(256, 4)
k3_kernel(const float* __restrict__ Wo, float* __restrict__ out2, float* __restrict__ out3)
{
    int blk = blockIdx.x;
    if (blk < 256) {
        // 16 n-stripes x 16 K-splits (chunk 64)
        int n0 = (blk & 15) * 32, s = blk >> 4;
        gemm128<0>(g_t2buf, HD, Wo, HD, out2, DOUT, n0, s * 64, 4, nullptr, nullptr);
    } else {
        int id = blk - 256;
        int n0 = (id & 15) * 32, s = id >> 4;
        gemm128<2>(g_xq, HD, g_Wc, HD, out3, DOUT, n0, s * 64, 4, g_s2, g_t2a);
    }
}

// =====================================================================
extern "C" void kernel_launch(void* const* d_in, const int* in_sizes, int n_in,
                              void* d_out, int out_size) {
    const float* x    = (const float*)d_in[0];
    const float* k    = (const float*)d_in[1];
    const float* bn1g = (const float*)d_in[2];
    const float* bn1b = (const float*)d_in[3];
    const float* Wx   = (const float*)d_in[4];
    const float* bx   = (const float*)d_in[5];
    const float* Wk   = (const float*)d_in[6];
    const float* bk   = (const float*)d_in[7];
    const float* bn2g = (const float*)d_in[8];
    const float* bn2b = (const float*)d_in[9];
    const float* Wlin = (const float*)d_in[10];
    const float* blin = (const float*)d_in[11];
    const float* Wo   = (const float*)d_in[12];
    const float* bo   = (const float*)d_in[13];
    float* out = (float*)d_out;

    float* attn_out = out;                       // (128,16,1024) == all ones
    float* out2 = out + (size_t)BB * NH * NKK;   // (128,512)
    float* out3 = out2 + (size_t)BB * DOUT;      // (128,512)

    k0_kernel<<<480, 256>>>(x, bn1g, bn1b, Wo, bk, blin, bo, bx);
    k1_kernel<<<2560, 256>>>(x, k, Wx, Wlin, Wo, (float4*)attn_out, out2, out3);
    k2_kernel<<<320, 256>>>(bn2g, bn2b, Wk);
    k3_kernel<<<512, 256>>>(Wo, out2, out3);

    (void)in_sizes; (void)n_in; (void)out_size;
}